// round 1
// baseline (speedup 1.0000x reference)
#include <cuda_runtime.h>
#include <math.h>

// ---------------------------------------------------------------------------
// Fused MlpExtractor: trunk(128->128->62 tanh) + value(62->128 tanh) +
// noisy gating (E=2) + experts(62->64 relu ->6 softmax) + dense combine.
// One CTA = 128 rows, 256 threads, all GEMMs via smem-staged 8x8 reg tiles.
// Output packing: [action B*6 | latent_vf B*128 | expout B*2*6]  (fp32)
// ---------------------------------------------------------------------------

static constexpr int ROWS = 128;
static constexpr int TPB  = 256;

static constexpr int SA_STRIDE = 132;  // 128 + 4 pad (bank-conflict relief)
static constexpr int SL_STRIDE = 68;   // 64 + 4 pad

static constexpr int SA_OFF   = 0;                          // 128*132
static constexpr int SW_OFF   = SA_OFF + 128 * SA_STRIDE;   // 128*128
static constexpr int SL_OFF   = SW_OFF + 128 * 128;         // 128*68
static constexpr int SG_OFF   = SL_OFF + 128 * SL_STRIDE;   // 256 gates
static constexpr int SACT_OFF = SG_OFF + 256;               // 128*12 action partials
static constexpr int SW2_OFF  = SACT_OFF + 128 * 12;        // 768 We2 + 12 be2 (+pad)
static constexpr int SMEM_FLOATS = SW2_OFF + 784;
static constexpr int SMEM_BYTES  = SMEM_FLOATS * 4;         // 178240 B

__device__ __forceinline__ float softplusf(float x) {
    // matches jax.nn.softplus: max(x,0) + log1p(exp(-|x|))
    return fmaxf(x, 0.f) + log1pf(expf(-fabsf(x)));
}

// C[8x8] += A[8 rows x K] * B[K x 8 cols], A/B in shared memory.
template <int K, int AS, int BS>
__device__ __forceinline__ void gemm8x8(const float* __restrict__ A,
                                        const float* __restrict__ Bm,
                                        int ty, int tx, float acc[8][8]) {
#pragma unroll 1
    for (int k = 0; k < K; k += 4) {
        float4 a4[8];
#pragma unroll
        for (int i = 0; i < 8; i++)
            a4[i] = *(const float4*)(A + (ty * 8 + i) * AS + k);
#pragma unroll
        for (int kk = 0; kk < 4; kk++) {
            float4 b0 = *(const float4*)(Bm + (k + kk) * BS + tx * 8);
            float4 b1 = *(const float4*)(Bm + (k + kk) * BS + tx * 8 + 4);
            float bvv[8] = {b0.x, b0.y, b0.z, b0.w, b1.x, b1.y, b1.z, b1.w};
#pragma unroll
            for (int i = 0; i < 8; i++) {
                float a = (kk == 0) ? a4[i].x : (kk == 1) ? a4[i].y
                         : (kk == 2) ? a4[i].z : a4[i].w;
#pragma unroll
                for (int j = 0; j < 8; j++)
                    acc[i][j] = fmaf(a, bvv[j], acc[i][j]);
            }
        }
    }
}

// C[8x4] += A[8 rows x K] * B[K x 4 cols]
template <int K, int AS, int BS>
__device__ __forceinline__ void gemm8x4(const float* __restrict__ A,
                                        const float* __restrict__ Bm,
                                        int ty, int tx, float acc[8][4]) {
#pragma unroll 1
    for (int k = 0; k < K; k += 4) {
        float4 a4[8];
#pragma unroll
        for (int i = 0; i < 8; i++)
            a4[i] = *(const float4*)(A + (ty * 8 + i) * AS + k);
#pragma unroll
        for (int kk = 0; kk < 4; kk++) {
            float4 b0 = *(const float4*)(Bm + (k + kk) * BS + tx * 4);
            float bvv[4] = {b0.x, b0.y, b0.z, b0.w};
#pragma unroll
            for (int i = 0; i < 8; i++) {
                float a = (kk == 0) ? a4[i].x : (kk == 1) ? a4[i].y
                         : (kk == 2) ? a4[i].z : a4[i].w;
#pragma unroll
                for (int j = 0; j < 4; j++)
                    acc[i][j] = fmaf(a, bvv[j], acc[i][j]);
            }
        }
    }
}

__global__ void __launch_bounds__(TPB, 1) mlp_fused_kernel(
    const float* __restrict__ feat,   const float* __restrict__ noise,
    const float* __restrict__ Ws0,    const float* __restrict__ bs0,
    const float* __restrict__ Ws1,    const float* __restrict__ bs1,
    const float* __restrict__ Wv,     const float* __restrict__ bv,
    const float* __restrict__ w_gate, const float* __restrict__ w_noise,
    const float* __restrict__ We1,    const float* __restrict__ be1,
    const float* __restrict__ We2,    const float* __restrict__ be2,
    float* __restrict__ out_action, float* __restrict__ out_vf,
    float* __restrict__ out_expout)
{
    extern __shared__ float sm[];
    float* sA   = sm + SA_OFF;    // feat -> h -> eh   [128][132]
    float* sW   = sm + SW_OFF;    // staged weights    [128][128] max
    float* sL   = sm + SL_OFF;    // latent (padded)   [128][68]
    float* sG   = sm + SG_OFF;    // gates             [128][2]
    float* sAct = sm + SACT_OFF;  // gate*expout       [128][12]
    float* sW2  = sm + SW2_OFF;   // We2 (768) + be2 (12)

    const int tid  = threadIdx.x;
    const int row0 = blockIdx.x * ROWS;
    const int tx = tid & 15, ty = tid >> 4;

    // ---- stage features, Ws0, We2/be2 ----
    for (int i = tid; i < ROWS * 32; i += TPB) {
        int r = i >> 5, c4 = (i & 31) << 2;
        *(float4*)&sA[r * SA_STRIDE + c4] =
            *(const float4*)&feat[(size_t)(row0 + r) * 128 + c4];
    }
    for (int i = tid; i < 128 * 32; i += TPB) {
        int r = i >> 5, c4 = (i & 31) << 2;
        *(float4*)&sW[r * 128 + c4] = *(const float4*)&Ws0[r * 128 + c4];
    }
    for (int i = tid; i < 768; i += TPB) sW2[i] = We2[i];
    if (tid < 12) sW2[768 + tid] = be2[tid];
    __syncthreads();

    // ================= Phase A: h = tanh(feat @ Ws0 + bs0) =================
    float acc[8][8];
#pragma unroll
    for (int i = 0; i < 8; i++)
#pragma unroll
        for (int j = 0; j < 8; j++) acc[i][j] = 0.f;
    gemm8x8<128, SA_STRIDE, 128>(sA, sW, ty, tx, acc);
    __syncthreads();
    {
        float bb[8];
#pragma unroll
        for (int j = 0; j < 8; j++) bb[j] = bs0[tx * 8 + j];
#pragma unroll
        for (int i = 0; i < 8; i++)
#pragma unroll
            for (int j = 0; j < 8; j++)
                sA[(ty * 8 + i) * SA_STRIDE + tx * 8 + j] = tanhf(acc[i][j] + bb[j]);
    }
    // stage Ws1 (padded to [128][64]) into sW
    for (int i = tid; i < 128 * 64; i += TPB) {
        int k = i >> 6, c = i & 63;
        sW[i] = (c < 62) ? Ws1[k * 62 + c] : 0.f;
    }
    __syncthreads();

    // ================= Phase B: latent = tanh(h @ Ws1 + bs1) ===============
    float accB[8][4];
#pragma unroll
    for (int i = 0; i < 8; i++)
#pragma unroll
        for (int j = 0; j < 4; j++) accB[i][j] = 0.f;
    gemm8x4<128, SA_STRIDE, 64>(sA, sW, ty, tx, accB);
    __syncthreads();
    {
        float bb[4];
#pragma unroll
        for (int j = 0; j < 4; j++) {
            int c = tx * 4 + j;
            bb[j] = (c < 62) ? bs1[c] : 0.f;
        }
#pragma unroll
        for (int i = 0; i < 8; i++)
#pragma unroll
            for (int j = 0; j < 4; j++)
                sL[(ty * 8 + i) * SL_STRIDE + tx * 4 + j] = tanhf(accB[i][j] + bb[j]);
    }
    // stage Wv (padded to [64][128]) into sW
    for (int i = tid; i < 64 * 32; i += TPB) {
        int k = i >> 5, c4 = (i & 31) << 2;
        float4 v = make_float4(0.f, 0.f, 0.f, 0.f);
        if (k < 62) v = *(const float4*)&Wv[k * 128 + c4];
        *(float4*)&sW[k * 128 + c4] = v;
    }
    __syncthreads();

    // ============ Phase D: noisy gating (one thread per row) ===============
    if (tid < 128) {
        float c0 = 0.f, c1 = 0.f, n0 = 0.f, n1 = 0.f;
        const float* lrow = &sL[tid * SL_STRIDE];
#pragma unroll 2
        for (int k = 0; k < 62; k++) {
            float l = lrow[k];
            c0 = fmaf(l, w_gate[2 * k + 0], c0);
            c1 = fmaf(l, w_gate[2 * k + 1], c1);
            n0 = fmaf(l, w_noise[2 * k + 0], n0);
            n1 = fmaf(l, w_noise[2 * k + 1], n1);
        }
        float s0 = softplusf(n0) + 1e-2f;
        float s1 = softplusf(n1) + 1e-2f;
        float z0 = fmaf(noise[(size_t)(row0 + tid) * 2 + 0], s0, c0);
        float z1 = fmaf(noise[(size_t)(row0 + tid) * 2 + 1], s1, c1);
        float m  = fmaxf(z0, z1);
        float e0 = expf(z0 - m), e1 = expf(z1 - m);
        float inv = 1.f / (e0 + e1);
        sG[2 * tid + 0] = e0 * inv;
        sG[2 * tid + 1] = e1 * inv;
    }

    // ============ Phase C: latent_vf = tanh(latent @ Wv + bv) ==============
#pragma unroll
    for (int i = 0; i < 8; i++)
#pragma unroll
        for (int j = 0; j < 8; j++) acc[i][j] = 0.f;
    gemm8x8<64, SL_STRIDE, 128>(sL, sW, ty, tx, acc);
    __syncthreads();
    {
        float bb[8];
#pragma unroll
        for (int j = 0; j < 8; j++) bb[j] = bv[tx * 8 + j];
#pragma unroll
        for (int i = 0; i < 8; i++) {
            float4 v0, v1;
            v0.x = tanhf(acc[i][0] + bb[0]);
            v0.y = tanhf(acc[i][1] + bb[1]);
            v0.z = tanhf(acc[i][2] + bb[2]);
            v0.w = tanhf(acc[i][3] + bb[3]);
            v1.x = tanhf(acc[i][4] + bb[4]);
            v1.y = tanhf(acc[i][5] + bb[5]);
            v1.z = tanhf(acc[i][6] + bb[6]);
            v1.w = tanhf(acc[i][7] + bb[7]);
            size_t g = (size_t)(row0 + ty * 8 + i) * 128 + tx * 8;
            *(float4*)&out_vf[g]     = v0;
            *(float4*)&out_vf[g + 4] = v1;
        }
    }
    // stage We1 concat (padded to [64][128], cols = e*64+hid) into sW
    for (int i = tid; i < 64 * 128; i += TPB) {
        int k = i >> 7, c = i & 127;
        int e = c >> 6, hid = c & 63;
        sW[i] = (k < 62) ? We1[((e * 62 + k) << 6) + hid] : 0.f;
    }
    __syncthreads();

    // ========= Phase E: eh = relu(latent @ We1 + be1)  [128][2*64] =========
#pragma unroll
    for (int i = 0; i < 8; i++)
#pragma unroll
        for (int j = 0; j < 8; j++) acc[i][j] = 0.f;
    gemm8x8<64, SL_STRIDE, 128>(sL, sW, ty, tx, acc);
    {
        float bb[8];
#pragma unroll
        for (int j = 0; j < 8; j++) bb[j] = be1[tx * 8 + j];  // be1 flat [2*64]
#pragma unroll
        for (int i = 0; i < 8; i++)
#pragma unroll
            for (int j = 0; j < 8; j++)
                sA[(ty * 8 + i) * SA_STRIDE + tx * 8 + j] =
                    fmaxf(acc[i][j] + bb[j], 0.f);
    }
    __syncthreads();

    // ====== Phase F: expout softmax + gated combine (thread=(row,e)) =======
    {
        int row = tid >> 1, e = tid & 1;
        float lg[6];
#pragma unroll
        for (int o = 0; o < 6; o++) lg[o] = sW2[768 + e * 6 + o];
        const float* ehrow = &sA[row * SA_STRIDE + e * 64];
        const float* w2    = &sW2[e * 64 * 6];
#pragma unroll 8
        for (int h = 0; h < 64; h++) {
            float x = ehrow[h];
#pragma unroll
            for (int o = 0; o < 6; o++) lg[o] = fmaf(x, w2[h * 6 + o], lg[o]);
        }
        float m = lg[0];
#pragma unroll
        for (int o = 1; o < 6; o++) m = fmaxf(m, lg[o]);
        float p[6], s = 0.f;
#pragma unroll
        for (int o = 0; o < 6; o++) { p[o] = expf(lg[o] - m); s += p[o]; }
        float inv = 1.f / s;
        float g = sG[tid];  // sG[row*2+e]
        size_t gbase = ((size_t)(row0 + row) * 2 + e) * 6;
#pragma unroll
        for (int o = 0; o < 6; o++) {
            float po = p[o] * inv;
            out_expout[gbase + o] = po;
            sAct[tid * 6 + o] = g * po;
        }
    }
    __syncthreads();
    if (tid < 128) {
        size_t gbase = (size_t)(row0 + tid) * 6;
#pragma unroll
        for (int o = 0; o < 6; o++)
            out_action[gbase + o] = sAct[tid * 12 + o] + sAct[tid * 12 + 6 + o];
    }
}

extern "C" void kernel_launch(void* const* d_in, const int* in_sizes, int n_in,
                              void* d_out, int out_size) {
    const float* feat    = (const float*)d_in[0];
    const float* noise   = (const float*)d_in[1];
    const float* Ws0     = (const float*)d_in[2];
    const float* bs0     = (const float*)d_in[3];
    const float* Ws1     = (const float*)d_in[4];
    const float* bs1     = (const float*)d_in[5];
    const float* Wv      = (const float*)d_in[6];
    const float* bv      = (const float*)d_in[7];
    const float* w_gate  = (const float*)d_in[8];
    const float* w_noise = (const float*)d_in[9];
    const float* We1     = (const float*)d_in[10];
    const float* be1     = (const float*)d_in[11];
    const float* We2     = (const float*)d_in[12];
    const float* be2     = (const float*)d_in[13];

    const int B = in_sizes[0] / 128;

    float* out        = (float*)d_out;
    float* out_action = out;                       // [B,6]
    float* out_vf     = out + (size_t)B * 6;       // [B,128]
    float* out_expout = out + (size_t)B * 134;     // [B,2,6]

    cudaFuncSetAttribute(mlp_fused_kernel,
                         cudaFuncAttributeMaxDynamicSharedMemorySize, SMEM_BYTES);

    mlp_fused_kernel<<<B / ROWS, TPB, SMEM_BYTES>>>(
        feat, noise, Ws0, bs0, Ws1, bs1, Wv, bv, w_gate, w_noise,
        We1, be1, We2, be2, out_action, out_vf, out_expout);
}